// round 4
// baseline (speedup 1.0000x reference)
#include <cuda_runtime.h>

#define HID   512
#define NH    16
#define HD    32
#define SEQ   1024
#define BATCH 2
#define MROWS (BATCH*SEQ)   // 2048
#define WIN   256           // gamma^256 ~ 2e-12: beyond-window terms negligible

// scratch (no allocations allowed)
__device__ float g_q[MROWS*HID];
__device__ float g_k[MROWS*HID];
__device__ float g_v[MROWS*HID];
__device__ float g_att[MROWS*HID];

// ---------------------------------------------------------------------------
// C[M,N] = A[M,K] @ W[K,N] + bias[N]   (row-major, M=2048, N=K=512)
// 64x64 block tile, BK=16, 256 threads, 4x4 per-thread microtile.
// ---------------------------------------------------------------------------
__global__ __launch_bounds__(256) void gemm_bias_kernel(
    const float* __restrict__ A, const float* __restrict__ W,
    const float* __restrict__ bias, float* __restrict__ C)
{
    const int K = 512, N = 512;
    __shared__ float As[16][64];   // [k][m]
    __shared__ float Bs[16][64];   // [k][n]

    const int tid = threadIdx.x;
    const int m0 = blockIdx.y * 64;
    const int n0 = blockIdx.x * 64;
    const int ty = tid >> 4;        // 0..15
    const int tx = tid & 15;        // 0..15

    // load indices
    const int ai = tid >> 2;            // row in A tile 0..63
    const int aj = (tid & 3) * 4;       // k offset 0,4,8,12
    const int bj = tid >> 4;            // k row 0..15
    const int bn = (tid & 15) * 4;      // col offset

    float acc[4][4];
    #pragma unroll
    for (int i = 0; i < 4; i++)
        #pragma unroll
        for (int j = 0; j < 4; j++) acc[i][j] = 0.f;

    for (int k0 = 0; k0 < K; k0 += 16) {
        float4 av = *(const float4*)&A[(m0 + ai) * K + k0 + aj];
        As[aj+0][ai] = av.x; As[aj+1][ai] = av.y;
        As[aj+2][ai] = av.z; As[aj+3][ai] = av.w;
        *(float4*)&Bs[bj][bn] = *(const float4*)&W[(k0 + bj) * N + n0 + bn];
        __syncthreads();

        #pragma unroll
        for (int kk = 0; kk < 16; kk++) {
            float4 a4 = *(const float4*)&As[kk][ty * 4];
            float4 b4 = *(const float4*)&Bs[kk][tx * 4];
            float a[4] = {a4.x, a4.y, a4.z, a4.w};
            float b[4] = {b4.x, b4.y, b4.z, b4.w};
            #pragma unroll
            for (int i = 0; i < 4; i++)
                #pragma unroll
                for (int j = 0; j < 4; j++)
                    acc[i][j] += a[i] * b[j];
        }
        __syncthreads();
    }

    #pragma unroll
    for (int i = 0; i < 4; i++) {
        const int row = m0 + ty * 4 + i;
        #pragma unroll
        for (int j = 0; j < 4; j++) {
            const int col = n0 + tx * 4 + j;
            C[row * N + col] = acc[i][j] + bias[col];
        }
    }
}

// ---------------------------------------------------------------------------
// Banded quadratic attention: out_t = sum_{s in (t-WIN, t]} gamma^{t-s} (q.k)^2 v_s
// grid: (SEQ/64, BATCH*NH). 256 threads: 64 queries x 4 lanes, each lane owns
// 8 of the 32 output dims. Dot product reduced across the 4 lanes via shfl.
// ---------------------------------------------------------------------------
__global__ __launch_bounds__(256) void attn_kernel()
{
    __shared__ float ks[64][32];
    __shared__ float vs[64][32];
    __shared__ float gtab[WIN];

    const int tid = threadIdx.x;
    const int bh = blockIdx.y;
    const int b  = bh >> 4;
    const int h  = bh & 15;
    const int t0 = blockIdx.x * 64;

    // gamma powers: exp(i * ln(0.9))
    gtab[tid] = __expf((float)tid * -0.10536051565782628f);

    const int qi = tid >> 2;   // query within tile
    const int l4 = tid & 3;    // dim quarter
    const int t  = t0 + qi;

    const float* qrow = &g_q[(size_t)(b * SEQ + t) * HID + h * HD + l4 * 8];
    const float4 q1 = *(const float4*)qrow;
    const float4 q2 = *(const float4*)(qrow + 4);

    float acc[8];
    #pragma unroll
    for (int j = 0; j < 8; j++) acc[j] = 0.f;

    const int st0 = (t0 - WIN + 1 > 0 ? t0 - WIN + 1 : 0) >> 6;
    const int st1 = t0 >> 6;

    // tile-load indices
    const int r = tid >> 2;          // row 0..63
    const int c = (tid & 3) * 8;     // col 0,8,16,24

    for (int st = st0; st <= st1; st++) {
        const int srow = st * 64 + r;
        const float* kp = &g_k[(size_t)(b * SEQ + srow) * HID + h * HD + c];
        const float* vp = &g_v[(size_t)(b * SEQ + srow) * HID + h * HD + c];
        *(float4*)&ks[r][c]     = *(const float4*)kp;
        *(float4*)&ks[r][c + 4] = *(const float4*)(kp + 4);
        *(float4*)&vs[r][c]     = *(const float4*)vp;
        *(float4*)&vs[r][c + 4] = *(const float4*)(vp + 4);
        __syncthreads();

        const int sbase = st * 64;
        #pragma unroll 4
        for (int s = 0; s < 64; s++) {
            const float4 k1 = *(const float4*)&ks[s][l4 * 8];
            const float4 k2 = *(const float4*)&ks[s][l4 * 8 + 4];
            float dot = q1.x * k1.x + q1.y * k1.y + q1.z * k1.z + q1.w * k1.w
                      + q2.x * k2.x + q2.y * k2.y + q2.z * k2.z + q2.w * k2.w;
            dot += __shfl_xor_sync(0xffffffffu, dot, 1);
            dot += __shfl_xor_sync(0xffffffffu, dot, 2);
            const int idx = t - (sbase + s);
            const float wgt = ((unsigned)idx < WIN) ? gtab[idx] * dot * dot : 0.f;
            const float4 v1 = *(const float4*)&vs[s][l4 * 8];
            const float4 v2 = *(const float4*)&vs[s][l4 * 8 + 4];
            acc[0] += wgt * v1.x; acc[1] += wgt * v1.y;
            acc[2] += wgt * v1.z; acc[3] += wgt * v1.w;
            acc[4] += wgt * v2.x; acc[5] += wgt * v2.y;
            acc[6] += wgt * v2.z; acc[7] += wgt * v2.w;
        }
        __syncthreads();
    }

    float* op = &g_att[(size_t)(b * SEQ + t) * HID + h * HD + l4 * 8];
    *(float4*)op       = make_float4(acc[0], acc[1], acc[2], acc[3]);
    *(float4*)(op + 4) = make_float4(acc[4], acc[5], acc[6], acc[7]);
}

// ---------------------------------------------------------------------------
extern "C" void kernel_launch(void* const* d_in, const int* in_sizes, int n_in,
                              void* d_out, int out_size)
{
    const float* x  = (const float*)d_in[0];
    const float* qw = (const float*)d_in[1];
    const float* qb = (const float*)d_in[2];
    const float* kw = (const float*)d_in[3];
    const float* kb = (const float*)d_in[4];
    const float* vw = (const float*)d_in[5];
    const float* vb = (const float*)d_in[6];
    const float* ow = (const float*)d_in[7];
    const float* ob = (const float*)d_in[8];
    float* out = (float*)d_out;

    float *pq, *pk, *pv, *pa;
    cudaGetSymbolAddress((void**)&pq, g_q);
    cudaGetSymbolAddress((void**)&pk, g_k);
    cudaGetSymbolAddress((void**)&pv, g_v);
    cudaGetSymbolAddress((void**)&pa, g_att);

    dim3 gg(HID / 64, MROWS / 64);   // (8, 32)
    gemm_bias_kernel<<<gg, 256>>>(x, qw, qb, pq);
    gemm_bias_kernel<<<gg, 256>>>(x, kw, kb, pk);
    gemm_bias_kernel<<<gg, 256>>>(x, vw, vb, pv);
    attn_kernel<<<dim3(SEQ / 64, BATCH * NH), 256>>>();
    gemm_bias_kernel<<<gg, 256>>>(pa, ow, ob, out);
}

// round 5
// speedup vs baseline: 1.1772x; 1.1772x over previous
#include <cuda_runtime.h>

#define HID   512
#define NH    16
#define HD    32
#define SEQ   1024
#define BATCH 2
#define MROWS (BATCH*SEQ)   // 2048
#define WIN   256           // gamma^256 ~ 2e-12: beyond-window terms negligible

// scratch (no allocations allowed)
__device__ float g_q[MROWS*HID];
__device__ float g_k[MROWS*HID];
__device__ float g_v[MROWS*HID];
__device__ float g_att[MROWS*HID];

// ---------------------------------------------------------------------------
// C[M,N] = A[M,K] @ W[K,N] + bias[N]   (row-major, M=2048, N=K=512)
// 64x64 block tile, BK=16, 128 threads, 4x8 per-thread microtile,
// double-buffered smem with register prefetch.
// ---------------------------------------------------------------------------
__global__ __launch_bounds__(128) void gemm_bias_kernel(
    const float* __restrict__ A, const float* __restrict__ W,
    const float* __restrict__ bias, float* __restrict__ C)
{
    const int K = 512, N = 512;
    __shared__ float As[2][16][64];   // [buf][k][m]
    __shared__ float Bs[2][16][64];   // [buf][k][n]

    const int tid = threadIdx.x;
    const int m0 = blockIdx.y * 64;
    const int n0 = blockIdx.x * 64;
    const int tr = tid & 15;        // row group (4 rows)
    const int tc = tid >> 4;        // col group 0..7 (8 cols)

    // A-tile load: 64 rows x 16 k, each thread 2 float4
    const int ai = tid >> 1;            // row 0..63
    const int aj = (tid & 1) * 8;       // k offset 0 or 8
    // B-tile load: 16 rows x 64 n
    const int bk = tid >> 3;            // k row 0..15
    const int bn = (tid & 7) * 8;       // col offset

    float acc[4][8];
    #pragma unroll
    for (int i = 0; i < 4; i++)
        #pragma unroll
        for (int j = 0; j < 8; j++) acc[i][j] = 0.f;

    // prologue: load first k-tile into buffer 0
    float4 a0 = *(const float4*)&A[(size_t)(m0 + ai) * K + aj];
    float4 a1 = *(const float4*)&A[(size_t)(m0 + ai) * K + aj + 4];
    float4 b0 = *(const float4*)&W[(size_t)bk * N + n0 + bn];
    float4 b1 = *(const float4*)&W[(size_t)bk * N + n0 + bn + 4];
    As[0][aj+0][ai] = a0.x; As[0][aj+1][ai] = a0.y;
    As[0][aj+2][ai] = a0.z; As[0][aj+3][ai] = a0.w;
    As[0][aj+4][ai] = a1.x; As[0][aj+5][ai] = a1.y;
    As[0][aj+6][ai] = a1.z; As[0][aj+7][ai] = a1.w;
    *(float4*)&Bs[0][bk][bn]     = b0;
    *(float4*)&Bs[0][bk][bn + 4] = b1;
    __syncthreads();

    for (int k0 = 0; k0 < K; k0 += 16) {
        const int buf = (k0 >> 4) & 1;
        const int nxt = buf ^ 1;
        const bool more = (k0 + 16 < K);
        if (more) {
            const int kn = k0 + 16;
            a0 = *(const float4*)&A[(size_t)(m0 + ai) * K + kn + aj];
            a1 = *(const float4*)&A[(size_t)(m0 + ai) * K + kn + aj + 4];
            b0 = *(const float4*)&W[(size_t)(kn + bk) * N + n0 + bn];
            b1 = *(const float4*)&W[(size_t)(kn + bk) * N + n0 + bn + 4];
        }

        #pragma unroll
        for (int kk = 0; kk < 16; kk++) {
            float4 a4  = *(const float4*)&As[buf][kk][tr * 4];
            float4 bb0 = *(const float4*)&Bs[buf][kk][tc * 8];
            float4 bb1 = *(const float4*)&Bs[buf][kk][tc * 8 + 4];
            float av[4] = {a4.x, a4.y, a4.z, a4.w};
            float bv[8] = {bb0.x, bb0.y, bb0.z, bb0.w, bb1.x, bb1.y, bb1.z, bb1.w};
            #pragma unroll
            for (int i = 0; i < 4; i++)
                #pragma unroll
                for (int j = 0; j < 8; j++)
                    acc[i][j] += av[i] * bv[j];
        }

        if (more) {
            As[nxt][aj+0][ai] = a0.x; As[nxt][aj+1][ai] = a0.y;
            As[nxt][aj+2][ai] = a0.z; As[nxt][aj+3][ai] = a0.w;
            As[nxt][aj+4][ai] = a1.x; As[nxt][aj+5][ai] = a1.y;
            As[nxt][aj+6][ai] = a1.z; As[nxt][aj+7][ai] = a1.w;
            *(float4*)&Bs[nxt][bk][bn]     = b0;
            *(float4*)&Bs[nxt][bk][bn + 4] = b1;
        }
        __syncthreads();
    }

    #pragma unroll
    for (int i = 0; i < 4; i++) {
        const int row = m0 + tr * 4 + i;
        float4 o0, o1;
        o0.x = acc[i][0] + bias[n0 + tc*8 + 0];
        o0.y = acc[i][1] + bias[n0 + tc*8 + 1];
        o0.z = acc[i][2] + bias[n0 + tc*8 + 2];
        o0.w = acc[i][3] + bias[n0 + tc*8 + 3];
        o1.x = acc[i][4] + bias[n0 + tc*8 + 4];
        o1.y = acc[i][5] + bias[n0 + tc*8 + 5];
        o1.z = acc[i][6] + bias[n0 + tc*8 + 6];
        o1.w = acc[i][7] + bias[n0 + tc*8 + 7];
        *(float4*)&C[(size_t)row * N + n0 + tc*8]     = o0;
        *(float4*)&C[(size_t)row * N + n0 + tc*8 + 4] = o1;
    }
}

// ---------------------------------------------------------------------------
// Banded quadratic attention, GEMM-style:
//   out_t = sum_{s in (t-WIN, t]} gamma^(t-s) (q_t . k_s)^2 v_s
// Per block: one (b,h) x 64-query tile. Per KV tile:
//   phase 1: S[64x64] = Q K^T  (16x16 threads, 4x4 microtile, transposed smem)
//            weight: w = gtab[t-s] * S^2 (masked), stored transposed Ws[s][q]
//   phase 2: O[64x32] += Ws^T V (16 q-groups x 16 d-pairs, 4x2 microtile)
// ---------------------------------------------------------------------------
__global__ __launch_bounds__(256) void attn_kernel()
{
    __shared__ float Qs[32][64];     // [d][q]
    __shared__ float Ks[32][64];     // [d][s]
    __shared__ float Vs[64][32];     // [s][d]
    __shared__ float Ws[64][64];     // [s][q]
    __shared__ float gtab[WIN];

    const int tid = threadIdx.x;
    const int bh = blockIdx.y;
    const int b  = bh >> 4;
    const int h  = bh & 15;
    const int t0 = blockIdx.x * 64;

    gtab[tid] = __expf((float)tid * -0.10536051565782628f); // gamma^i

    // tile-load indices: r = row 0..63, c = dim offset {0,8,16,24}
    const int r = tid >> 2;
    const int c = (tid & 3) * 8;

    // load Q tile transposed (once per block)
    {
        const float* qp = &g_q[(size_t)(b * SEQ + t0 + r) * HID + h * HD + c];
        float4 q1 = *(const float4*)qp;
        float4 q2 = *(const float4*)(qp + 4);
        Qs[c+0][r] = q1.x; Qs[c+1][r] = q1.y; Qs[c+2][r] = q1.z; Qs[c+3][r] = q1.w;
        Qs[c+4][r] = q2.x; Qs[c+5][r] = q2.y; Qs[c+6][r] = q2.z; Qs[c+7][r] = q2.w;
    }

    const int tq = tid & 15;   // phase-1 q group
    const int ts = tid >> 4;   // phase-1 s group
    const int tr = tid & 15;   // phase-2 q group
    const int tc = tid >> 4;   // phase-2 d pair (0..15)

    float oacc[4][2];
    #pragma unroll
    for (int i = 0; i < 4; i++) { oacc[i][0] = 0.f; oacc[i][1] = 0.f; }

    const int lo  = t0 - WIN + 1;
    const int st0 = (lo > 0 ? lo : 0) >> 6;
    const int st1 = t0 >> 6;

    for (int st = st0; st <= st1; st++) {
        const int sbase = st * 64;
        // load K (transposed) and V tiles
        {
            const float* kp = &g_k[(size_t)(b * SEQ + sbase + r) * HID + h * HD + c];
            float4 k1 = *(const float4*)kp;
            float4 k2 = *(const float4*)(kp + 4);
            Ks[c+0][r] = k1.x; Ks[c+1][r] = k1.y; Ks[c+2][r] = k1.z; Ks[c+3][r] = k1.w;
            Ks[c+4][r] = k2.x; Ks[c+5][r] = k2.y; Ks[c+6][r] = k2.z; Ks[c+7][r] = k2.w;
            const float* vp = &g_v[(size_t)(b * SEQ + sbase + r) * HID + h * HD + c];
            *(float4*)&Vs[r][c]     = *(const float4*)vp;
            *(float4*)&Vs[r][c + 4] = *(const float4*)(vp + 4);
        }
        __syncthreads();

        // phase 1: scores 4x4 per thread
        float s[4][4];
        #pragma unroll
        for (int i = 0; i < 4; i++)
            #pragma unroll
            for (int j = 0; j < 4; j++) s[i][j] = 0.f;

        #pragma unroll
        for (int d = 0; d < 32; d++) {
            float4 qa = *(const float4*)&Qs[d][tq * 4];
            float4 ka = *(const float4*)&Ks[d][ts * 4];
            float qv[4] = {qa.x, qa.y, qa.z, qa.w};
            float kv[4] = {ka.x, ka.y, ka.z, ka.w};
            #pragma unroll
            for (int i = 0; i < 4; i++)
                #pragma unroll
                for (int j = 0; j < 4; j++)
                    s[i][j] += qv[i] * kv[j];
        }

        // weight + transposed store
        #pragma unroll
        for (int i = 0; i < 4; i++) {
            const int t = t0 + tq * 4 + i;
            #pragma unroll
            for (int j = 0; j < 4; j++) {
                const int idx = t - (sbase + ts * 4 + j);
                const float sv = s[i][j];
                Ws[ts*4 + j][tq*4 + i] =
                    ((unsigned)idx < WIN) ? gtab[idx] * sv * sv : 0.f;
            }
        }
        __syncthreads();

        // phase 2: O += Ws^T V, 4 queries x 2 dims per thread
        #pragma unroll 8
        for (int s2 = 0; s2 < 64; s2++) {
            float4 w4 = *(const float4*)&Ws[s2][tr * 4];
            float2 vv = *(const float2*)&Vs[s2][tc * 2];
            oacc[0][0] += w4.x * vv.x; oacc[0][1] += w4.x * vv.y;
            oacc[1][0] += w4.y * vv.x; oacc[1][1] += w4.y * vv.y;
            oacc[2][0] += w4.z * vv.x; oacc[2][1] += w4.z * vv.y;
            oacc[3][0] += w4.w * vv.x; oacc[3][1] += w4.w * vv.y;
        }
        __syncthreads();
    }

    #pragma unroll
    for (int i = 0; i < 4; i++) {
        const int t = t0 + tr * 4 + i;
        float2 o = make_float2(oacc[i][0], oacc[i][1]);
        *(float2*)&g_att[(size_t)(b * SEQ + t) * HID + h * HD + tc * 2] = o;
    }
}

// ---------------------------------------------------------------------------
extern "C" void kernel_launch(void* const* d_in, const int* in_sizes, int n_in,
                              void* d_out, int out_size)
{
    const float* x  = (const float*)d_in[0];
    const float* qw = (const float*)d_in[1];
    const float* qb = (const float*)d_in[2];
    const float* kw = (const float*)d_in[3];
    const float* kb = (const float*)d_in[4];
    const float* vw = (const float*)d_in[5];
    const float* vb = (const float*)d_in[6];
    const float* ow = (const float*)d_in[7];
    const float* ob = (const float*)d_in[8];
    float* out = (float*)d_out;

    float *pq, *pk, *pv, *pa;
    cudaGetSymbolAddress((void**)&pq, g_q);
    cudaGetSymbolAddress((void**)&pk, g_k);
    cudaGetSymbolAddress((void**)&pv, g_v);
    cudaGetSymbolAddress((void**)&pa, g_att);

    dim3 gg(HID / 64, MROWS / 64);   // (8, 32)
    gemm_bias_kernel<<<gg, 128>>>(x, qw, qb, pq);
    gemm_bias_kernel<<<gg, 128>>>(x, kw, kb, pk);
    gemm_bias_kernel<<<gg, 128>>>(x, vw, vb, pv);
    attn_kernel<<<dim3(SEQ / 64, BATCH * NH), 256>>>();
    gemm_bias_kernel<<<gg, 128>>>(pa, ow, ob, out);
}

// round 9
// speedup vs baseline: 1.2678x; 1.0770x over previous
#include <cuda_runtime.h>

#define HID   512
#define NH    16
#define HD    32
#define SEQ   1024
#define BATCH 2
#define MROWS (BATCH*SEQ)   // 2048
#define WIN   256           // gamma^256 ~ 2e-12: beyond-window terms negligible

// scratch (no allocations allowed)
__device__ float g_q[MROWS*HID];
__device__ float g_k[MROWS*HID];
__device__ float g_v[MROWS*HID];
__device__ float g_att[MROWS*HID];

typedef unsigned long long u64;

// ---- packed f32x2 helpers (SASS FFMA2 — only reachable via PTX) ----------
__device__ __forceinline__ u64 pack2(float lo, float hi) {
    u64 r; asm("mov.b64 %0,{%1,%2};" : "=l"(r) : "f"(lo), "f"(hi)); return r;
}
__device__ __forceinline__ float2 unpack2(u64 v) {
    float2 r; asm("mov.b64 {%0,%1},%2;" : "=f"(r.x), "=f"(r.y) : "l"(v)); return r;
}
__device__ __forceinline__ u64 ffma2(u64 a, u64 b, u64 c) {
    u64 d; asm("fma.rn.f32x2 %0,%1,%2,%3;" : "=l"(d) : "l"(a), "l"(b), "l"(c)); return d;
}
__device__ __forceinline__ u64 bcast2(float v) { return pack2(v, v); }

// ---------------------------------------------------------------------------
// C[M,N] = A[M,K] @ W[K,N] + bias[N]   (row-major, M=2048, N=K=512)
// 128x64 block tile, BK=16, 128 threads, 8x8 per-thread microtile in f32x2
// pairs (pairs along M), double-buffered smem with register prefetch.
// ---------------------------------------------------------------------------
__global__ __launch_bounds__(128) void gemm_bias_kernel(
    const float* __restrict__ A, const float* __restrict__ W,
    const float* __restrict__ bias, float* __restrict__ C)
{
    const int K = 512, N = 512;
    __shared__ __align__(16) float As[2][16][128];   // [buf][k][m]
    __shared__ __align__(16) float Bs[2][16][64];    // [buf][k][n]

    const int tid = threadIdx.x;
    const int m0 = blockIdx.y * 128;
    const int n0 = blockIdx.x * 64;
    const int tr  = tid & 15;        // m-group: 8 rows = 4 pairs
    const int tcg = tid >> 4;        // n-group: 8 cols

    // A load: thread owns one row (m0+tid), 16 k values (4 float4)
    // B load: bk = k-row, bn = n-offset (8 floats = 2 float4)
    const int bk = tid >> 3;
    const int bn = (tid & 7) * 8;

    u64 acc[4][8];
    #pragma unroll
    for (int i = 0; i < 4; i++)
        #pragma unroll
        for (int j = 0; j < 8; j++) acc[i][j] = 0ull;

    float4 a0, a1, a2, a3, b0, b1;
    // prologue: tile 0
    {
        const float* ap = &A[(size_t)(m0 + tid) * K];
        a0 = *(const float4*)(ap + 0);
        a1 = *(const float4*)(ap + 4);
        a2 = *(const float4*)(ap + 8);
        a3 = *(const float4*)(ap + 12);
        b0 = *(const float4*)&W[(size_t)bk * N + n0 + bn];
        b1 = *(const float4*)&W[(size_t)bk * N + n0 + bn + 4];
        As[0][0][tid]  = a0.x; As[0][1][tid]  = a0.y; As[0][2][tid]  = a0.z; As[0][3][tid]  = a0.w;
        As[0][4][tid]  = a1.x; As[0][5][tid]  = a1.y; As[0][6][tid]  = a1.z; As[0][7][tid]  = a1.w;
        As[0][8][tid]  = a2.x; As[0][9][tid]  = a2.y; As[0][10][tid] = a2.z; As[0][11][tid] = a2.w;
        As[0][12][tid] = a3.x; As[0][13][tid] = a3.y; As[0][14][tid] = a3.z; As[0][15][tid] = a3.w;
        *(float4*)&Bs[0][bk][bn]     = b0;
        *(float4*)&Bs[0][bk][bn + 4] = b1;
    }
    __syncthreads();

    for (int k0 = 0; k0 < K; k0 += 16) {
        const int buf = (k0 >> 4) & 1;
        const int nxt = buf ^ 1;
        const bool more = (k0 + 16 < K);
        if (more) {
            const int kn = k0 + 16;
            const float* ap = &A[(size_t)(m0 + tid) * K + kn];
            a0 = *(const float4*)(ap + 0);
            a1 = *(const float4*)(ap + 4);
            a2 = *(const float4*)(ap + 8);
            a3 = *(const float4*)(ap + 12);
            b0 = *(const float4*)&W[(size_t)(kn + bk) * N + n0 + bn];
            b1 = *(const float4*)&W[(size_t)(kn + bk) * N + n0 + bn + 4];
        }

        #pragma unroll
        for (int kk = 0; kk < 16; kk++) {
            ulonglong2 al = *(const ulonglong2*)&As[buf][kk][tr * 8];
            ulonglong2 ah = *(const ulonglong2*)&As[buf][kk][tr * 8 + 4];
            float4 bb0 = *(const float4*)&Bs[buf][kk][tcg * 8];
            float4 bb1 = *(const float4*)&Bs[buf][kk][tcg * 8 + 4];
            u64 ap2[4] = {al.x, al.y, ah.x, ah.y};
            u64 bp[8]  = {bcast2(bb0.x), bcast2(bb0.y), bcast2(bb0.z), bcast2(bb0.w),
                          bcast2(bb1.x), bcast2(bb1.y), bcast2(bb1.z), bcast2(bb1.w)};
            #pragma unroll
            for (int i = 0; i < 4; i++)
                #pragma unroll
                for (int j = 0; j < 8; j++)
                    acc[i][j] = ffma2(ap2[i], bp[j], acc[i][j]);
        }

        if (more) {
            As[nxt][0][tid]  = a0.x; As[nxt][1][tid]  = a0.y; As[nxt][2][tid]  = a0.z; As[nxt][3][tid]  = a0.w;
            As[nxt][4][tid]  = a1.x; As[nxt][5][tid]  = a1.y; As[nxt][6][tid]  = a1.z; As[nxt][7][tid]  = a1.w;
            As[nxt][8][tid]  = a2.x; As[nxt][9][tid]  = a2.y; As[nxt][10][tid] = a2.z; As[nxt][11][tid] = a2.w;
            As[nxt][12][tid] = a3.x; As[nxt][13][tid] = a3.y; As[nxt][14][tid] = a3.z; As[nxt][15][tid] = a3.w;
            *(float4*)&Bs[nxt][bk][bn]     = b0;
            *(float4*)&Bs[nxt][bk][bn + 4] = b1;
        }
        __syncthreads();
    }

    // epilogue: unpack pairs, add bias, vector stores
    float bias8[8];
    #pragma unroll
    for (int j = 0; j < 8; j++) bias8[j] = bias[n0 + tcg * 8 + j];

    #pragma unroll
    for (int p = 0; p < 4; p++) {
        float2 u[8];
        #pragma unroll
        for (int j = 0; j < 8; j++) u[j] = unpack2(acc[p][j]);
        const int row_lo = m0 + tr * 8 + 2 * p;
        float4 lo0 = make_float4(u[0].x + bias8[0], u[1].x + bias8[1],
                                 u[2].x + bias8[2], u[3].x + bias8[3]);
        float4 lo1 = make_float4(u[4].x + bias8[4], u[5].x + bias8[5],
                                 u[6].x + bias8[6], u[7].x + bias8[7]);
        float4 hi0 = make_float4(u[0].y + bias8[0], u[1].y + bias8[1],
                                 u[2].y + bias8[2], u[3].y + bias8[3]);
        float4 hi1 = make_float4(u[4].y + bias8[4], u[5].y + bias8[5],
                                 u[6].y + bias8[6], u[7].y + bias8[7]);
        *(float4*)&C[(size_t)row_lo * N + n0 + tcg * 8]           = lo0;
        *(float4*)&C[(size_t)row_lo * N + n0 + tcg * 8 + 4]       = lo1;
        *(float4*)&C[(size_t)(row_lo + 1) * N + n0 + tcg * 8]     = hi0;
        *(float4*)&C[(size_t)(row_lo + 1) * N + n0 + tcg * 8 + 4] = hi1;
    }
}

// ---------------------------------------------------------------------------
// Banded quadratic attention, GEMM-style with f32x2:
//   out_t = sum_{s in (t-WIN, t]} gamma^(t-s) (q_t . k_s)^2 v_s
// 128 threads per (b,h,64-query-tile) block.
//   phase 1: S[64x64] = Q K^T; 8 q-groups x 16 s-groups, 8q(4 pairs)x4s each
//   weight:  w = gtab[t-s] * S^2 (masked), stored transposed Ws[s][q]
//   phase 2: O[64x32] += Ws^T V; 16 q-groups x 8 d-groups, 4q(2 pairs)x4d each
// ---------------------------------------------------------------------------
__global__ __launch_bounds__(128) void attn_kernel()
{
    __shared__ __align__(16) float Qs[32][64];     // [d][q]
    __shared__ __align__(16) float Ks[32][64];     // [d][s]
    __shared__ __align__(16) float Vs[64][32];     // [s][d]
    __shared__ __align__(16) float Ws[64][64];     // [s][q]
    __shared__ float gtab[WIN];

    const int tid = threadIdx.x;
    const int bh = blockIdx.y;
    const int b  = bh >> 4;
    const int h  = bh & 15;
    const int t0 = blockIdx.x * 64;

    gtab[tid]       = __expf((float)tid * -0.10536051565782628f);
    gtab[tid + 128] = __expf((float)(tid + 128) * -0.10536051565782628f);

    // tile-load map: r = row 0..63, c = dim offset {0,16}
    const int r = tid >> 1;
    const int c = (tid & 1) * 16;

    // load Q tile transposed (once per block)
    {
        const float* qp = &g_q[(size_t)(b * SEQ + t0 + r) * HID + h * HD + c];
        #pragma unroll
        for (int v = 0; v < 4; v++) {
            float4 q4 = *(const float4*)(qp + v * 4);
            Qs[c + v*4 + 0][r] = q4.x; Qs[c + v*4 + 1][r] = q4.y;
            Qs[c + v*4 + 2][r] = q4.z; Qs[c + v*4 + 3][r] = q4.w;
        }
    }

    const int tq  = tid >> 4;    // phase-1 q group (8 queries = 4 pairs)
    const int ts  = tid & 15;    // phase-1 s group (4)
    const int tq2 = tid & 15;    // phase-2 q group (4 queries = 2 pairs)
    const int td  = tid >> 4;    // phase-2 d group (4)

    u64 op[2][4];
    #pragma unroll
    for (int i = 0; i < 2; i++)
        #pragma unroll
        for (int j = 0; j < 4; j++) op[i][j] = 0ull;

    const int lo  = t0 - WIN + 1;
    const int st0 = (lo > 0 ? lo : 0) >> 6;
    const int st1 = t0 >> 6;

    for (int st = st0; st <= st1; st++) {
        const int sbase = st * 64;
        // load K (transposed) and V tiles
        {
            const float* kp = &g_k[(size_t)(b * SEQ + sbase + r) * HID + h * HD + c];
            #pragma unroll
            for (int v = 0; v < 4; v++) {
                float4 k4 = *(const float4*)(kp + v * 4);
                Ks[c + v*4 + 0][r] = k4.x; Ks[c + v*4 + 1][r] = k4.y;
                Ks[c + v*4 + 2][r] = k4.z; Ks[c + v*4 + 3][r] = k4.w;
            }
            const float* vp = &g_v[(size_t)(b * SEQ + sbase + r) * HID + h * HD + c];
            *(float4*)&Vs[r][c]      = *(const float4*)vp;
            *(float4*)&Vs[r][c + 4]  = *(const float4*)(vp + 4);
            *(float4*)&Vs[r][c + 8]  = *(const float4*)(vp + 8);
            *(float4*)&Vs[r][c + 12] = *(const float4*)(vp + 12);
        }
        __syncthreads();

        // phase 1: scores, 4 q-pairs x 4 s per thread
        u64 sp[4][4];
        #pragma unroll
        for (int i = 0; i < 4; i++)
            #pragma unroll
            for (int j = 0; j < 4; j++) sp[i][j] = 0ull;

        #pragma unroll
        for (int d = 0; d < 32; d++) {
            ulonglong2 ql = *(const ulonglong2*)&Qs[d][tq * 8];
            ulonglong2 qh = *(const ulonglong2*)&Qs[d][tq * 8 + 4];
            float4 k4 = *(const float4*)&Ks[d][ts * 4];
            u64 qp2[4] = {ql.x, ql.y, qh.x, qh.y};
            u64 kp2[4] = {bcast2(k4.x), bcast2(k4.y), bcast2(k4.z), bcast2(k4.w)};
            #pragma unroll
            for (int i = 0; i < 4; i++)
                #pragma unroll
                for (int j = 0; j < 4; j++)
                    sp[i][j] = ffma2(qp2[i], kp2[j], sp[i][j]);
        }

        // weight + transposed store
        #pragma unroll
        for (int i = 0; i < 4; i++) {
            const int q_lo = tq * 8 + 2 * i;
            const int t_lo = t0 + q_lo;
            #pragma unroll
            for (int j = 0; j < 4; j++) {
                const int sg = sbase + ts * 4 + j;
                float2 sv = unpack2(sp[i][j]);
                const int idx0 = t_lo - sg;
                const int idx1 = idx0 + 1;
                float w0 = ((unsigned)idx0 < WIN) ? gtab[idx0] * sv.x * sv.x : 0.f;
                float w1 = ((unsigned)idx1 < WIN) ? gtab[idx1] * sv.y * sv.y : 0.f;
                Ws[ts * 4 + j][q_lo]     = w0;
                Ws[ts * 4 + j][q_lo + 1] = w1;
            }
        }
        __syncthreads();

        // phase 2: O += Ws^T V, 2 q-pairs x 4 dims per thread
        #pragma unroll 8
        for (int s2 = 0; s2 < 64; s2++) {
            ulonglong2 wp = *(const ulonglong2*)&Ws[s2][tq2 * 4];
            float4 v4 = *(const float4*)&Vs[s2][td * 4];
            u64 vp2[4] = {bcast2(v4.x), bcast2(v4.y), bcast2(v4.z), bcast2(v4.w)};
            u64 wpp[2] = {wp.x, wp.y};
            #pragma unroll
            for (int i = 0; i < 2; i++)
                #pragma unroll
                for (int j = 0; j < 4; j++)
                    op[i][j] = ffma2(wpp[i], vp2[j], op[i][j]);
        }
        __syncthreads();
    }

    // epilogue: unpack and store 4 rows x 4 dims
    #pragma unroll
    for (int i = 0; i < 2; i++) {
        float2 u[4];
        #pragma unroll
        for (int j = 0; j < 4; j++) u[j] = unpack2(op[i][j]);
        const int t_lo = t0 + tq2 * 4 + 2 * i;
        float4 olo = make_float4(u[0].x, u[1].x, u[2].x, u[3].x);
        float4 ohi = make_float4(u[0].y, u[1].y, u[2].y, u[3].y);
        *(float4*)&g_att[(size_t)(b * SEQ + t_lo) * HID + h * HD + td * 4]       = olo;
        *(float4*)&g_att[(size_t)(b * SEQ + t_lo + 1) * HID + h * HD + td * 4]   = ohi;
    }
}

// ---------------------------------------------------------------------------
extern "C" void kernel_launch(void* const* d_in, const int* in_sizes, int n_in,
                              void* d_out, int out_size)
{
    const float* x  = (const float*)d_in[0];
    const float* qw = (const float*)d_in[1];
    const float* qb = (const float*)d_in[2];
    const float* kw = (const float*)d_in[3];
    const float* kb = (const float*)d_in[4];
    const float* vw = (const float*)d_in[5];
    const float* vb = (const float*)d_in[6];
    const float* ow = (const float*)d_in[7];
    const float* ob = (const float*)d_in[8];
    float* out = (float*)d_out;

    float *pq, *pk, *pv, *pa;
    cudaGetSymbolAddress((void**)&pq, g_q);
    cudaGetSymbolAddress((void**)&pk, g_k);
    cudaGetSymbolAddress((void**)&pv, g_v);
    cudaGetSymbolAddress((void**)&pa, g_att);

    dim3 gg(HID / 64, MROWS / 128);   // (8, 16) = 128 blocks
    gemm_bias_kernel<<<gg, 128>>>(x, qw, qb, pq);
    gemm_bias_kernel<<<gg, 128>>>(x, kw, kb, pk);
    gemm_bias_kernel<<<gg, 128>>>(x, vw, vb, pv);
    attn_kernel<<<dim3(SEQ / 64, BATCH * NH), 128>>>();
    gemm_bias_kernel<<<gg, 128>>>(pa, ow, ob, out);
}

// round 11
// speedup vs baseline: 1.3976x; 1.1024x over previous
#include <cuda_runtime.h>

#define HID   512
#define NH    16
#define HD    32
#define SEQ   1024
#define BATCH 2
#define MROWS (BATCH*SEQ)   // 2048
#define WIN   128           // gamma^128/(1-gamma) ~ 1.4e-5: safe truncation

// scratch (no allocations allowed)
__device__ float g_q[MROWS*HID];
__device__ float g_k[MROWS*HID];
__device__ float g_v[MROWS*HID];
__device__ float g_att[MROWS*HID];

typedef unsigned long long u64;

#define LOG2G (-0.15200309344504995f)   // log2(0.9)

// ---- packed f32x2 helpers (SASS FFMA2 — only reachable via PTX) ----------
__device__ __forceinline__ u64 pack2(float lo, float hi) {
    u64 r; asm("mov.b64 %0,{%1,%2};" : "=l"(r) : "f"(lo), "f"(hi)); return r;
}
__device__ __forceinline__ float2 unpack2(u64 v) {
    float2 r; asm("mov.b64 {%0,%1},%2;" : "=f"(r.x), "=f"(r.y) : "l"(v)); return r;
}
__device__ __forceinline__ u64 ffma2(u64 a, u64 b, u64 c) {
    u64 d; asm("fma.rn.f32x2 %0,%1,%2,%3;" : "=l"(d) : "l"(a), "l"(b), "l"(c)); return d;
}

// ---------------------------------------------------------------------------
// C[M,N] = A[M,K] @ W[K,N] + bias[N]   (row-major, M=2048, N=K=512)
// 128x64 block tile, BK=16, 256 threads, 4x8 microtile (f32x2 pairs along M).
// B stored in smem PRE-DUPLICATED as {b,b} u64 pairs -> no bcast MOVs, and
// B reads are warp-broadcast (tcg constant per warp). blockIdx.z selects one
// of up to 3 weight/bias/output sets (fused QKV).
// ---------------------------------------------------------------------------
__global__ __launch_bounds__(256) void gemm_bias_kernel(
    const float* __restrict__ A,
    const float* __restrict__ W0, const float* __restrict__ B0, float* __restrict__ C0,
    const float* __restrict__ W1, const float* __restrict__ B1, float* __restrict__ C1,
    const float* __restrict__ W2, const float* __restrict__ B2, float* __restrict__ C2)
{
    const int K = 512, N = 512;
    const float* W = W0; const float* bias = B0; float* C = C0;
    if (blockIdx.z == 1) { W = W1; bias = B1; C = C1; }
    else if (blockIdx.z == 2) { W = W2; bias = B2; C = C2; }

    __shared__ __align__(16) float As[2][16][128];   // 16 KB
    __shared__ __align__(16) u64   Bs[2][16][64];    // 16 KB (duplicated pairs)

    const int tid = threadIdx.x;
    const int m0 = blockIdx.y * 128;
    const int n0 = blockIdx.x * 64;
    const int tr  = tid & 31;        // m-group: 4 rows = 2 pairs
    const int tcg = tid >> 5;        // n-group: 8 cols (constant per warp)

    // A load: row = tid>>1 (0..127), k-offset = (tid&1)*8 : 2 float4
    const int ar = tid >> 1;
    const int ak = (tid & 1) * 8;
    // B load: bk = tid>>4 (0..15), bn = (tid&15)*4 : 1 float4
    const int bk = tid >> 4;
    const int bn = (tid & 15) * 4;

    u64 acc[2][8];
    #pragma unroll
    for (int i = 0; i < 2; i++)
        #pragma unroll
        for (int j = 0; j < 8; j++) acc[i][j] = 0ull;

    float4 a0, a1, b0;
    {   // prologue: tile 0
        const float* ap = &A[(size_t)(m0 + ar) * K + ak];
        a0 = *(const float4*)(ap + 0);
        a1 = *(const float4*)(ap + 4);
        b0 = *(const float4*)&W[(size_t)bk * N + n0 + bn];
        As[0][ak+0][ar] = a0.x; As[0][ak+1][ar] = a0.y;
        As[0][ak+2][ar] = a0.z; As[0][ak+3][ar] = a0.w;
        As[0][ak+4][ar] = a1.x; As[0][ak+5][ar] = a1.y;
        As[0][ak+6][ar] = a1.z; As[0][ak+7][ar] = a1.w;
        *(ulonglong2*)&Bs[0][bk][bn]     = make_ulonglong2(pack2(b0.x,b0.x), pack2(b0.y,b0.y));
        *(ulonglong2*)&Bs[0][bk][bn + 2] = make_ulonglong2(pack2(b0.z,b0.z), pack2(b0.w,b0.w));
    }
    __syncthreads();

    for (int k0 = 0; k0 < K; k0 += 16) {
        const int buf = (k0 >> 4) & 1;
        const int nxt = buf ^ 1;
        const bool more = (k0 + 16 < K);
        if (more) {
            const int kn = k0 + 16;
            const float* ap = &A[(size_t)(m0 + ar) * K + kn + ak];
            a0 = *(const float4*)(ap + 0);
            a1 = *(const float4*)(ap + 4);
            b0 = *(const float4*)&W[(size_t)(kn + bk) * N + n0 + bn];
        }

        #pragma unroll
        for (int kk = 0; kk < 16; kk++) {
            ulonglong2 a2  = *(const ulonglong2*)&As[buf][kk][tr * 4];
            ulonglong2 b01 = *(const ulonglong2*)&Bs[buf][kk][tcg * 8];
            ulonglong2 b23 = *(const ulonglong2*)&Bs[buf][kk][tcg * 8 + 2];
            ulonglong2 b45 = *(const ulonglong2*)&Bs[buf][kk][tcg * 8 + 4];
            ulonglong2 b67 = *(const ulonglong2*)&Bs[buf][kk][tcg * 8 + 6];
            u64 ap2[2] = {a2.x, a2.y};
            u64 bp[8]  = {b01.x, b01.y, b23.x, b23.y, b45.x, b45.y, b67.x, b67.y};
            #pragma unroll
            for (int i = 0; i < 2; i++)
                #pragma unroll
                for (int j = 0; j < 8; j++)
                    acc[i][j] = ffma2(ap2[i], bp[j], acc[i][j]);
        }

        if (more) {
            As[nxt][ak+0][ar] = a0.x; As[nxt][ak+1][ar] = a0.y;
            As[nxt][ak+2][ar] = a0.z; As[nxt][ak+3][ar] = a0.w;
            As[nxt][ak+4][ar] = a1.x; As[nxt][ak+5][ar] = a1.y;
            As[nxt][ak+6][ar] = a1.z; As[nxt][ak+7][ar] = a1.w;
            *(ulonglong2*)&Bs[nxt][bk][bn]     = make_ulonglong2(pack2(b0.x,b0.x), pack2(b0.y,b0.y));
            *(ulonglong2*)&Bs[nxt][bk][bn + 2] = make_ulonglong2(pack2(b0.z,b0.z), pack2(b0.w,b0.w));
        }
        __syncthreads();
    }

    // epilogue
    float bias8[8];
    #pragma unroll
    for (int j = 0; j < 8; j++) bias8[j] = bias[n0 + tcg * 8 + j];

    #pragma unroll
    for (int p = 0; p < 2; p++) {
        float2 u[8];
        #pragma unroll
        for (int j = 0; j < 8; j++) u[j] = unpack2(acc[p][j]);
        const int row_lo = m0 + tr * 4 + 2 * p;
        float4 lo0 = make_float4(u[0].x + bias8[0], u[1].x + bias8[1],
                                 u[2].x + bias8[2], u[3].x + bias8[3]);
        float4 lo1 = make_float4(u[4].x + bias8[4], u[5].x + bias8[5],
                                 u[6].x + bias8[6], u[7].x + bias8[7]);
        float4 hi0 = make_float4(u[0].y + bias8[0], u[1].y + bias8[1],
                                 u[2].y + bias8[2], u[3].y + bias8[3]);
        float4 hi1 = make_float4(u[4].y + bias8[4], u[5].y + bias8[5],
                                 u[6].y + bias8[6], u[7].y + bias8[7]);
        *(float4*)&C[(size_t)row_lo * N + n0 + tcg * 8]           = lo0;
        *(float4*)&C[(size_t)row_lo * N + n0 + tcg * 8 + 4]       = lo1;
        *(float4*)&C[(size_t)(row_lo + 1) * N + n0 + tcg * 8]     = hi0;
        *(float4*)&C[(size_t)(row_lo + 1) * N + n0 + tcg * 8 + 4] = hi1;
    }
}

// ---------------------------------------------------------------------------
// Banded quadratic attention with f32x2 + duplicated-pair smem:
//   out_t = sum_{s<=t, t-s<window} gamma^(t-s) (q_t . k_s)^2 v_s
// 128 threads per (64-query-tile, b, h) block; ~3 KV tiles each (WIN=128).
//   phase 1: S = Q K^T; 8 q-groups x 16 s-groups, 8q(4 pairs) x 4s
//            K stored duplicated -> FFMA2 b-operand read directly, no MOVs
//   weight:  w = gamma^(t-s) * S^2 via precomputed power factors, no exp/gtab;
//            causal mask only on the diagonal tile; stored transposed Ws[s][q]
//   phase 2: O += Ws^T V; 16 q-groups x 8 d-groups, 4q(2 pairs) x 4d,
//            V stored duplicated
// ---------------------------------------------------------------------------
#define ATTN_SMEM (8192 + 16384 + 16384 + 16384)   // Qs + Ks2 + Vs2 + Ws = 56 KB

__global__ __launch_bounds__(128) void attn_kernel()
{
    extern __shared__ __align__(16) char smem[];
    float (*Qs)[64]  = (float (*)[64])(smem);                 // [32][64] floats
    u64   (*Ks2)[64] = (u64   (*)[64])(smem + 8192);          // [32][64] dup pairs
    u64   (*Vs2)[32] = (u64   (*)[32])(smem + 8192 + 16384);  // [64][32] dup pairs
    float (*Ws)[64]  = (float (*)[64])(smem + 8192 + 32768);  // [64][64]

    const int tid = threadIdx.x;
    const int bh = blockIdx.y;
    const int b  = bh >> 4;
    const int h  = bh & 15;
    const int t0 = blockIdx.x * 64;

    // tile-load map: r = row 0..63, c = dim offset {0,16}
    const int r = tid >> 1;
    const int c = (tid & 1) * 16;

    // load Q tile transposed (once per block)
    {
        const float* qp = &g_q[(size_t)(b * SEQ + t0 + r) * HID + h * HD + c];
        #pragma unroll
        for (int v = 0; v < 4; v++) {
            float4 q4 = *(const float4*)(qp + v * 4);
            Qs[c + v*4 + 0][r] = q4.x; Qs[c + v*4 + 1][r] = q4.y;
            Qs[c + v*4 + 2][r] = q4.z; Qs[c + v*4 + 3][r] = q4.w;
        }
    }

    const int tq  = tid >> 4;    // phase-1 q group (8 queries = 4 pairs)
    const int ts  = tid & 15;    // phase-1 s group (4)
    const int tq2 = tid & 15;    // phase-2 q group (4 queries = 2 pairs)
    const int td  = tid >> 4;    // phase-2 d group (4 dims)

    // decay factor precompute: gamma^(t-s) = gamma^(q_local) * gamma^(t0-sbase) * gamma^(-s_local)
    float gqv[8], ginv[4];
    #pragma unroll
    for (int u = 0; u < 8; u++) gqv[u] = exp2f((float)(tq * 8 + u) * LOG2G);
    #pragma unroll
    for (int j = 0; j < 4; j++) ginv[j] = exp2f((float)(-(ts * 4 + j)) * LOG2G);

    u64 op[2][4];
    #pragma unroll
    for (int i = 0; i < 2; i++)
        #pragma unroll
        for (int j = 0; j < 4; j++) op[i][j] = 0ull;

    const int lo  = t0 - WIN + 1;
    const int st0 = (lo > 0 ? lo : 0) >> 6;
    const int st1 = t0 >> 6;

    for (int st = st0; st <= st1; st++) {
        const int sbase = st * 64;
        // load K (transposed, duplicated) and V (duplicated) tiles
        {
            const float* kp = &g_k[(size_t)(b * SEQ + sbase + r) * HID + h * HD + c];
            #pragma unroll
            for (int v = 0; v < 4; v++) {
                float4 k4 = *(const float4*)(kp + v * 4);
                Ks2[c + v*4 + 0][r] = pack2(k4.x, k4.x);
                Ks2[c + v*4 + 1][r] = pack2(k4.y, k4.y);
                Ks2[c + v*4 + 2][r] = pack2(k4.z, k4.z);
                Ks2[c + v*4 + 3][r] = pack2(k4.w, k4.w);
            }
            const float* vp = &g_v[(size_t)(b * SEQ + sbase + r) * HID + h * HD + c];
            #pragma unroll
            for (int v = 0; v < 4; v++) {
                float4 v4 = *(const float4*)(vp + v * 4);
                *(ulonglong2*)&Vs2[r][c + v*4]     = make_ulonglong2(pack2(v4.x,v4.x), pack2(v4.y,v4.y));
                *(ulonglong2*)&Vs2[r][c + v*4 + 2] = make_ulonglong2(pack2(v4.z,v4.z), pack2(v4.w,v4.w));
            }
        }
        __syncthreads();

        // phase 1: scores, 4 q-pairs x 4 s per thread
        u64 sp[4][4];
        #pragma unroll
        for (int i = 0; i < 4; i++)
            #pragma unroll
            for (int j = 0; j < 4; j++) sp[i][j] = 0ull;

        #pragma unroll
        for (int d = 0; d < 32; d++) {
            ulonglong2 ql = *(const ulonglong2*)&Qs[d][tq * 8];
            ulonglong2 qh = *(const ulonglong2*)&Qs[d][tq * 8 + 4];
            ulonglong2 k2 = *(const ulonglong2*)&Ks2[d][ts * 4];
            ulonglong2 k3 = *(const ulonglong2*)&Ks2[d][ts * 4 + 2];
            u64 qp2[4] = {ql.x, ql.y, qh.x, qh.y};
            u64 kp2[4] = {k2.x, k2.y, k3.x, k3.y};
            #pragma unroll
            for (int i = 0; i < 4; i++)
                #pragma unroll
                for (int j = 0; j < 4; j++)
                    sp[i][j] = ffma2(qp2[i], kp2[j], sp[i][j]);
        }

        // weight + transposed store: w = s^2 * gamma^(q + (t0-sbase) - s)
        {
            const float gt = exp2f((float)(t0 - sbase) * LOG2G);
            float cq[8];
            #pragma unroll
            for (int u = 0; u < 8; u++) cq[u] = gqv[u] * gt;
            const bool diag = (st == st1);

            #pragma unroll
            for (int i = 0; i < 4; i++) {
                const int q_lo = tq * 8 + 2 * i;
                #pragma unroll
                for (int j = 0; j < 4; j++) {
                    const int sl = ts * 4 + j;
                    float2 sv = unpack2(sp[i][j]);
                    float w0 = sv.x * sv.x * cq[2*i]   * ginv[j];
                    float w1 = sv.y * sv.y * cq[2*i+1] * ginv[j];
                    if (diag) {
                        if (sl > q_lo)     w0 = 0.f;
                        if (sl > q_lo + 1) w1 = 0.f;
                    }
                    *(u64*)&Ws[sl][q_lo] = pack2(w0, w1);
                }
            }
        }
        __syncthreads();

        // phase 2: O += Ws^T V, 2 q-pairs x 4 dims per thread
        #pragma unroll 8
        for (int s2 = 0; s2 < 64; s2++) {
            ulonglong2 wp = *(const ulonglong2*)&Ws[s2][tq2 * 4];
            ulonglong2 v0 = *(const ulonglong2*)&Vs2[s2][td * 4];
            ulonglong2 v1 = *(const ulonglong2*)&Vs2[s2][td * 4 + 2];
            u64 wpp[2] = {wp.x, wp.y};
            u64 vp2[4] = {v0.x, v0.y, v1.x, v1.y};
            #pragma unroll
            for (int i = 0; i < 2; i++)
                #pragma unroll
                for (int j = 0; j < 4; j++)
                    op[i][j] = ffma2(wpp[i], vp2[j], op[i][j]);
        }
        __syncthreads();
    }

    // epilogue: unpack and store 4 rows x 4 dims
    #pragma unroll
    for (int i = 0; i < 2; i++) {
        float2 u[4];
        #pragma unroll
        for (int j = 0; j < 4; j++) u[j] = unpack2(op[i][j]);
        const int t_lo = t0 + tq2 * 4 + 2 * i;
        float4 olo = make_float4(u[0].x, u[1].x, u[2].x, u[3].x);
        float4 ohi = make_float4(u[0].y, u[1].y, u[2].y, u[3].y);
        *(float4*)&g_att[(size_t)(b * SEQ + t_lo) * HID + h * HD + td * 4]     = olo;
        *(float4*)&g_att[(size_t)(b * SEQ + t_lo + 1) * HID + h * HD + td * 4] = ohi;
    }
}

// ---------------------------------------------------------------------------
extern "C" void kernel_launch(void* const* d_in, const int* in_sizes, int n_in,
                              void* d_out, int out_size)
{
    const float* x  = (const float*)d_in[0];
    const float* qw = (const float*)d_in[1];
    const float* qb = (const float*)d_in[2];
    const float* kw = (const float*)d_in[3];
    const float* kb = (const float*)d_in[4];
    const float* vw = (const float*)d_in[5];
    const float* vb = (const float*)d_in[6];
    const float* ow = (const float*)d_in[7];
    const float* ob = (const float*)d_in[8];
    float* out = (float*)d_out;

    float *pq, *pk, *pv, *pa;
    cudaGetSymbolAddress((void**)&pq, g_q);
    cudaGetSymbolAddress((void**)&pk, g_k);
    cudaGetSymbolAddress((void**)&pv, g_v);
    cudaGetSymbolAddress((void**)&pa, g_att);

    cudaFuncSetAttribute(attn_kernel,
                         cudaFuncAttributeMaxDynamicSharedMemorySize, ATTN_SMEM);

    // fused QKV projections
    gemm_bias_kernel<<<dim3(8, 16, 3), 256>>>(x, qw, qb, pq, kw, kb, pk, vw, vb, pv);
    // banded quadratic attention
    attn_kernel<<<dim3(SEQ / 64, BATCH * NH), 128, ATTN_SMEM>>>();
    // output projection
    gemm_bias_kernel<<<dim3(8, 16, 1), 256>>>(pa, ow, ob, out,
                                              ow, ob, out, ow, ob, out);
}